// round 15
// baseline (speedup 1.0000x reference)
#include <cuda_runtime.h>
#include <cuda_fp16.h>
#include <cstdint>

#define NN 50000
#define NE 800000
#define H 4
#define D 64
#define HD 256
#define NEG_SLOPE 0.2f

// ---------------- scratch ----------------
__device__ __half g_fth[NN * HD];      // node projection, fp16 (gather payload)
__device__ float g_el[NN * H];
__device__ float g_er[NN * H];
__device__ float g_ee[8 * H];
__device__ float g_wl[256 * 8];        // folded W_fc@attn: [k][c], c<4: el heads, c>=4: er heads
__device__ int   g_deg[NN];
__device__ int   g_off[NN];
__device__ int   g_cur[NN];
__device__ int2  g_epk[NE];            // CSR-ordered {eid, (src<<3)|etype}
__device__ float g_aexp[NE * 4];       // CSR-ordered; after k_soft: NORMALIZED a
__device__ __half g_Ah[NN * 256];      // feat, fp16
__device__ __half g_Bh[256 * 256];     // W_fc, fp16

// ---------------- prep A: feat/W_fc fp16 convert (feeds GEMM) ----------------
__global__ void k_prep_split(const float* __restrict__ feat, const float* __restrict__ W_fc) {
    int b = blockIdx.x;
    float4 v;
    size_t i;
    __half* dh;
    if (b < 12500) {
        i = (size_t)b * 256 + threadIdx.x;
        v = ((const float4*)feat)[i];
        dh = g_Ah;
    } else {
        i = (size_t)(b - 12500) * 256 + threadIdx.x;
        v = ((const float4*)W_fc)[i];
        dh = g_Bh;
    }
    __half2 h0 = __floats2half2_rn(v.x, v.y);
    __half2 h1 = __floats2half2_rn(v.z, v.w);
    uint2 hp;
    hp.x = *(uint32_t*)&h0; hp.y = *(uint32_t*)&h1;
    *(uint2*)(dh + 4 * i) = hp;
}

// ---------------- fold W_fc with attn vectors (side stream, tiny) ----------------
__global__ void k_wl(const float* __restrict__ W_fc,
                     const float* __restrict__ attn_l, const float* __restrict__ attn_r) {
    int k = threadIdx.x;
    const float* row = W_fc + k * 256;
    #pragma unroll
    for (int h = 0; h < 4; h++) {
        float sl = 0.f, sr = 0.f;
        #pragma unroll 8
        for (int d = 0; d < 64; d++) {
            float w = row[h * 64 + d];
            sl += w * attn_l[h * 64 + d];
            sr += w * attn_r[h * 64 + d];
        }
        g_wl[k * 8 + h]     = sl;
        g_wl[k * 8 + 4 + h] = sr;
    }
}

// ---------------- el/er = feat @ wl (fp32 exact); warp per node, low-reg ----------------
__global__ void k_elr(const float* __restrict__ feat) {
    int w = (blockIdx.x * blockDim.x + threadIdx.x) >> 5;
    int lane = threadIdx.x & 31;
    if (w >= NN) return;
    const float4* fp = (const float4*)(feat + (size_t)w * 256 + lane * 8);
    float4 x0 = fp[0], x1 = fp[1];
    float f[8] = {x0.x, x0.y, x0.z, x0.w, x1.x, x1.y, x1.z, x1.w};
    float acc[8] = {0.f, 0.f, 0.f, 0.f, 0.f, 0.f, 0.f, 0.f};
    // wl chunk for this lane: k = lane*8 .. +7, 8 c-values per k = 64 floats.
    // Consume one float4 at a time (4 live regs; L1-broadcast across warps).
    const float4* wp = (const float4*)(g_wl + lane * 64);
    #pragma unroll
    for (int q = 0; q < 16; q++) {
        float4 wv = wp[q];
        float fj = f[q >> 1];
        int cb = (q & 1) * 4;
        acc[cb + 0] += fj * wv.x;
        acc[cb + 1] += fj * wv.y;
        acc[cb + 2] += fj * wv.z;
        acc[cb + 3] += fj * wv.w;
    }
    #pragma unroll
    for (int o = 16; o > 0; o >>= 1)
        #pragma unroll
        for (int c = 0; c < 8; c++) acc[c] += __shfl_xor_sync(0xffffffffu, acc[c], o);
    if (lane == 0) {
        *(float4*)(g_el + w * 4) = make_float4(acc[0], acc[1], acc[2], acc[3]);
        *(float4*)(g_er + w * 4) = make_float4(acc[4], acc[5], acc[6], acc[7]);
    }
}

// ---------------- prep B: ee table + degree count (feeds CSR chain) ----------------
__global__ void k_prep_misc(const float* __restrict__ edge_emb, const float* __restrict__ W_e,
                            const float* __restrict__ attn_e, const int* __restrict__ dst) {
    int b = blockIdx.x;
    if (b < 4) {
        int p = b * 8 + (threadIdx.x >> 5);
        int lane = threadIdx.x & 31;
        int t = p >> 2, h = p & 3;
        float acc0 = 0.f, acc1 = 0.f;
        int f0 = lane, f1 = lane + 32;
        #pragma unroll 4
        for (int k = 0; k < 64; k++) {
            float ek = edge_emb[t * 64 + k];
            acc0 += ek * W_e[k * 256 + h * 64 + f0];
            acc1 += ek * W_e[k * 256 + h * 64 + f1];
        }
        float v = acc0 * attn_e[h * 64 + f0] + acc1 * attn_e[h * 64 + f1];
        #pragma unroll
        for (int o = 16; o > 0; o >>= 1) v += __shfl_xor_sync(0xffffffffu, v, o);
        if (lane == 0) g_ee[t * 4 + h] = v;
    } else {
        int e = (b - 4) * 256 + threadIdx.x;
        if (e < NE) atomicAdd(&g_deg[dst[e]], 1);
    }
}

// ---------------- mma.sync fp16 GEMM (single pass), cp.async pipelined ----------------
#define ASTRIDE 80
#define BSTRIDE 272
#define ABUF 10240
#define BBUF 8704
#define SM_TOT2 (2*ABUF + 2*BBUF)

__device__ __forceinline__ void cpa16(uint32_t dst, const void* src) {
    asm volatile("cp.async.cg.shared.global [%0], [%1], 16;" :: "r"(dst), "l"(src));
}
__device__ __forceinline__ void ldsm_x4(uint32_t* r, uint32_t addr) {
    asm volatile("ldmatrix.sync.aligned.m8n8.x4.shared.b16 {%0,%1,%2,%3}, [%4];"
                 : "=r"(r[0]), "=r"(r[1]), "=r"(r[2]), "=r"(r[3]) : "r"(addr));
}
__device__ __forceinline__ void ldsm_x4t(uint32_t* r, uint32_t addr) {
    asm volatile("ldmatrix.sync.aligned.m8n8.x4.trans.shared.b16 {%0,%1,%2,%3}, [%4];"
                 : "=r"(r[0]), "=r"(r[1]), "=r"(r[2]), "=r"(r[3]) : "r"(addr));
}
__device__ __forceinline__ void mma_f16(float* c, const uint32_t* a, const uint32_t* b) {
    asm volatile(
        "mma.sync.aligned.m16n8k16.row.col.f32.f16.f16.f32 "
        "{%0,%1,%2,%3}, {%4,%5,%6,%7}, {%8,%9}, {%0,%1,%2,%3};"
        : "+f"(c[0]), "+f"(c[1]), "+f"(c[2]), "+f"(c[3])
        : "r"(a[0]), "r"(a[1]), "r"(a[2]), "r"(a[3]), "r"(b[0]), "r"(b[1]));
}

__global__ void __launch_bounds__(256, 2) k_gemm2() {
    extern __shared__ __align__(16) char smem[];
    uint32_t uA = (uint32_t)__cvta_generic_to_shared(smem);
    uint32_t uB = uA + 2 * ABUF;

    int tid = threadIdx.x, wid = tid >> 5, lane = tid & 31;
    int g = lane >> 2, tg = lane & 3;
    int bm = blockIdx.x * 128, bn = blockIdx.y * 128;
    int wm = (wid >> 1) * 32, wn = (wid & 1) * 64;

    uint32_t aBase = (wm + (lane & 7) + ((lane >> 3) & 1) * 8) * ASTRIDE + (lane >> 4) * 16;
    uint32_t bBase = (lane & 7) * BSTRIDE + wn * 2 + (lane >> 3) * 16;

    float acc[2][8][4];
    #pragma unroll
    for (int am = 0; am < 2; am++)
        #pragma unroll
        for (int nb = 0; nb < 8; nb++)
            #pragma unroll
            for (int q = 0; q < 4; q++) acc[am][nb][q] = 0.f;

    auto load_tile = [&](int it, int bf) {
        int k0 = it * 32;
        #pragma unroll
        for (int j = 0; j < 2; j++) {
            int idx = tid + j * 256;
            int row = idx >> 2, q = idx & 3;
            int gr = min(bm + row, NN - 1);
            cpa16(uA + bf * ABUF + row * ASTRIDE + q * 16,
                  g_Ah + (size_t)gr * 256 + k0 + q * 8);
        }
        #pragma unroll
        for (int j = 0; j < 2; j++) {
            int idx = tid + j * 256;
            int k = idx >> 4, n16 = idx & 15;
            cpa16(uB + bf * BBUF + k * BSTRIDE + n16 * 16,
                  g_Bh + (size_t)(k0 + k) * 256 + bn + n16 * 8);
        }
    };

    load_tile(0, 0);
    asm volatile("cp.async.commit_group;" ::: "memory");

    for (int it = 0; it < 8; it++) {
        if (it < 7) {
            load_tile(it + 1, (it + 1) & 1);
            asm volatile("cp.async.commit_group;" ::: "memory");
            asm volatile("cp.async.wait_group 1;" ::: "memory");
        } else {
            asm volatile("cp.async.wait_group 0;" ::: "memory");
        }
        __syncthreads();

        uint32_t aoff = (it & 1) * ABUF + aBase, boff = (it & 1) * BBUF + bBase;
        #pragma unroll
        for (int ks = 0; ks < 2; ks++) {
            uint32_t ah[2][4];
            #pragma unroll
            for (int am = 0; am < 2; am++)
                ldsm_x4(ah[am], uA + aoff + am * 16 * ASTRIDE + ks * 32);
            uint32_t bh[8][2];
            #pragma unroll
            for (int ng = 0; ng < 2; ng++)
                #pragma unroll
                for (int kh = 0; kh < 2; kh++) {
                    uint32_t r[4];
                    uint32_t off = boff + (ks * 16 + kh * 8) * BSTRIDE + ng * 64;
                    ldsm_x4t(r, uB + off);
                    #pragma unroll
                    for (int jj = 0; jj < 4; jj++) bh[ng * 4 + jj][kh] = r[jj];
                }
            #pragma unroll
            for (int am = 0; am < 2; am++)
                #pragma unroll
                for (int nb = 0; nb < 8; nb++) mma_f16(acc[am][nb], ah[am], bh[nb]);
        }
        __syncthreads();
    }

    // ---- epilogue: store g_fth (fp16) only ----
    #pragma unroll
    for (int am = 0; am < 2; am++) {
        #pragma unroll
        for (int rh = 0; rh < 2; rh++) {
            int row = bm + wm + am * 16 + g + rh * 8;
            if (row < NN) {
                #pragma unroll
                for (int nb = 0; nb < 8; nb++) {
                    float c0 = acc[am][nb][rh * 2 + 0];
                    float c1 = acc[am][nb][rh * 2 + 1];
                    int col = bn + wn + nb * 8 + 2 * tg;
                    *(__half2*)(g_fth + (size_t)row * 256 + col) = __floats2half2_rn(c0, c1);
                }
            }
        }
    }
}

// ---------------- CSR build ----------------
__global__ void k_scan() {
    __shared__ int ss[1024];
    const int CH = (NN + 1023) / 1024;
    int t = threadIdx.x;
    int b = t * CH, e = min(b + CH, NN);
    int s = 0;
    for (int i = b; i < e; i++) s += g_deg[i];
    ss[t] = s;
    __syncthreads();
    for (int o = 1; o < 1024; o <<= 1) {
        int v = (t >= o) ? ss[t - o] : 0;
        __syncthreads();
        ss[t] += v;
        __syncthreads();
    }
    int run = (t == 0) ? 0 : ss[t - 1];
    for (int i = b; i < e; i++) {
        g_off[i] = run;
        g_cur[i] = run;
        run += g_deg[i];
    }
}

__global__ void k_scatter(const int* __restrict__ dst, const int* __restrict__ src,
                          const int* __restrict__ ef) {
    int e = blockIdx.x * blockDim.x + threadIdx.x;
    if (e < NE) {
        int p = atomicAdd(&g_cur[dst[e]], 1);
        g_epk[p] = make_int2(e, (src[e] << 3) | (ef[e] & 7));
    }
}

// ---------------- softmax (passes 1+2): side stream, hidden under GEMM ----------------
__global__ void k_soft(float* __restrict__ out_a) {
    int n = (blockIdx.x * blockDim.x + threadIdx.x) >> 5;
    int lane = threadIdx.x & 31;
    if (n >= NN) return;
    int off = g_off[n], dg = g_deg[n];

    float4 erv = *(const float4*)(g_er + n * 4);
    float s0 = 0.f, s1 = 0.f, s2 = 0.f, s3 = 0.f;

    // pass 1: logits -> exp, store CSR-ordered (coalesced), accumulate sums
    for (int i = lane; i < dg; i += 32) {
        int pe = off + i;
        int2 pk = g_epk[pe];
        int s = pk.y >> 3, t = pk.y & 7;
        float4 elv = *(const float4*)(g_el + s * 4);
        float4 eev = *(const float4*)(g_ee + t * 4);
        float l0 = elv.x + erv.x + eev.x;
        float l1 = elv.y + erv.y + eev.y;
        float l2 = elv.z + erv.z + eev.z;
        float l3 = elv.w + erv.w + eev.w;
        l0 = l0 > 0.f ? l0 : NEG_SLOPE * l0;
        l1 = l1 > 0.f ? l1 : NEG_SLOPE * l1;
        l2 = l2 > 0.f ? l2 : NEG_SLOPE * l2;
        l3 = l3 > 0.f ? l3 : NEG_SLOPE * l3;
        float e0 = __expf(l0), e1 = __expf(l1), e2 = __expf(l2), e3 = __expf(l3);
        *(float4*)(g_aexp + (size_t)pe * 4) = make_float4(e0, e1, e2, e3);
        s0 += e0; s1 += e1; s2 += e2; s3 += e3;
    }
    #pragma unroll
    for (int o = 16; o > 0; o >>= 1) {
        s0 += __shfl_xor_sync(0xffffffffu, s0, o);
        s1 += __shfl_xor_sync(0xffffffffu, s1, o);
        s2 += __shfl_xor_sync(0xffffffffu, s2, o);
        s3 += __shfl_xor_sync(0xffffffffu, s3, o);
    }
    float i0 = (dg > 0) ? 1.f / s0 : 0.f;
    float i1 = (dg > 0) ? 1.f / s1 : 0.f;
    float i2 = (dg > 0) ? 1.f / s2 : 0.f;
    float i3 = (dg > 0) ? 1.f / s3 : 0.f;

    // pass 2: normalize IN PLACE (coalesced) + write out_a (random)
    for (int i = lane; i < dg; i += 32) {
        int pe = off + i;
        float4 v = *(const float4*)(g_aexp + (size_t)pe * 4);
        v.x *= i0; v.y *= i1; v.z *= i2; v.w *= i3;
        *(float4*)(g_aexp + (size_t)pe * 4) = v;
        int e = g_epk[pe].x;
        *(float4*)(out_a + (size_t)e * 4) = v;
    }
}

// ---------------- gather (pass 3): warp per node, after join ----------------
__global__ void k_gather(float* __restrict__ out_rst) {
    int n = (blockIdx.x * blockDim.x + threadIdx.x) >> 5;
    int lane = threadIdx.x & 31;
    if (n >= NN) return;
    int off = g_off[n], dg = g_deg[n];

    float acc[8] = {0.f, 0.f, 0.f, 0.f, 0.f, 0.f, 0.f, 0.f};
    int myh = lane >> 3;
    int boff = lane * 8;
    const __half* ftb = g_fth + boff;
    #pragma unroll 4
    for (int i = 0; i < dg; i++) {
        int pe = off + i;
        int s = g_epk[pe].y >> 3;
        float a = g_aexp[(size_t)pe * 4 + myh];   // already normalized
        float4 xr = *(const float4*)(ftb + (size_t)s * 256);   // 8 halfs
        const __half2* hp = (const __half2*)&xr;
        #pragma unroll
        for (int q = 0; q < 4; q++) {
            float2 f = __half22float2(hp[q]);
            acc[q * 2 + 0] += a * f.x;
            acc[q * 2 + 1] += a * f.y;
        }
    }
    float4* op = (float4*)(out_rst + (size_t)n * 256 + boff);
    op[0] = make_float4(acc[0], acc[1], acc[2], acc[3]);
    op[1] = make_float4(acc[4], acc[5], acc[6], acc[7]);

    // fused deg reset for next replay
    if (lane == 0) g_deg[n] = 0;
}

// ---------------- launch: fork-join (CSR + el/er + softmax under split+GEMM) ----------------
extern "C" void kernel_launch(void* const* d_in, const int* in_sizes, int n_in,
                              void* d_out, int out_size) {
    const float* feat     = (const float*)d_in[0];
    const int*   efeat    = (const int*)  d_in[1];
    const int*   src      = (const int*)  d_in[2];
    const int*   dst      = (const int*)  d_in[3];
    const float* W_fc     = (const float*)d_in[4];
    const float* W_e      = (const float*)d_in[5];
    const float* edge_emb = (const float*)d_in[6];
    const float* attn_l   = (const float*)d_in[7];
    const float* attn_r   = (const float*)d_in[8];
    const float* attn_e   = (const float*)d_in[9];

    float* out_rst = (float*)d_out;
    float* out_a   = (float*)d_out + (size_t)NN * HD;

    static cudaStream_t s2 = nullptr;
    static cudaEvent_t evF = nullptr, evJ = nullptr;
    if (!s2) {
        cudaStreamCreateWithFlags(&s2, cudaStreamNonBlocking);
        cudaEventCreateWithFlags(&evF, cudaEventDisableTiming);
        cudaEventCreateWithFlags(&evJ, cudaEventDisableTiming);
        cudaFuncSetAttribute(k_gemm2, cudaFuncAttributeMaxDynamicSharedMemorySize, SM_TOT2);
    }

    // fork: side = wl fold + el/er + CSR + softmax; main = fp16 convert + GEMM
    cudaEventRecord(evF, 0);
    cudaStreamWaitEvent(s2, evF, 0);

    k_wl<<<1, 256, 0, s2>>>(W_fc, attn_l, attn_r);
    k_elr<<<(NN * 32 + 255) / 256, 256, 0, s2>>>(feat);
    k_prep_misc<<<3129, 256, 0, s2>>>(edge_emb, W_e, attn_e, dst);
    k_scan<<<1, 1024, 0, s2>>>();
    k_scatter<<<3125, 256, 0, s2>>>(dst, src, efeat);
    k_soft<<<(NN * 32 + 255) / 256, 256, 0, s2>>>(out_a);
    cudaEventRecord(evJ, s2);

    k_prep_split<<<12564, 256>>>(feat, W_fc);
    k_gemm2<<<dim3(391, 2), 256, SM_TOT2>>>();

    // join: gather needs fth (main) + normalized aexp (side)
    cudaStreamWaitEvent(0, evJ, 0);
    k_gather<<<(NN * 32 + 255) / 256, 256>>>(out_rst);
}

// round 16
// speedup vs baseline: 2.4269x; 2.4269x over previous
#include <cuda_runtime.h>
#include <cuda_fp16.h>
#include <cstdint>

#define NN 50000
#define NE 800000
#define H 4
#define D 64
#define HD 256
#define NEG_SLOPE 0.2f
#define NB 196                 // scan blocks: 196*256 = 50176 >= NN

// ---------------- scratch ----------------
__device__ __half g_fth[NN * HD];      // node projection, fp16 (agg gather payload)
__device__ float g_el[NN * H];
__device__ float g_er[NN * H];
__device__ float g_ee[8 * H];
__device__ int   g_deg[NN];
__device__ int   g_off[NN];
__device__ int   g_cur[NN];
__device__ int   g_bsum[NB];
__device__ int   g_boff[NB];
__device__ int2  g_epk[NE];            // CSR-ordered {eid, (src<<3)|etype}
__device__ float g_aexp[NE * 4];       // CSR-ordered raw exp values
__device__ __half g_Ah[NN * 256];      // feat, fp16
__device__ __half g_Bh[256 * 256];     // W_fc, fp16

// ---------------- prep A: feat/W_fc fp16 convert (feeds GEMM) ----------------
__global__ void k_prep_split(const float* __restrict__ feat, const float* __restrict__ W_fc) {
    int b = blockIdx.x;
    float4 v;
    size_t i;
    __half* dh;
    if (b < 12500) {
        i = (size_t)b * 256 + threadIdx.x;
        v = ((const float4*)feat)[i];
        dh = g_Ah;
    } else {
        i = (size_t)(b - 12500) * 256 + threadIdx.x;
        v = ((const float4*)W_fc)[i];
        dh = g_Bh;
    }
    __half2 h0 = __floats2half2_rn(v.x, v.y);
    __half2 h1 = __floats2half2_rn(v.z, v.w);
    uint2 hp;
    hp.x = *(uint32_t*)&h0; hp.y = *(uint32_t*)&h1;
    *(uint2*)(dh + 4 * i) = hp;
}

// ---------------- prep B: ee table + degree count (feeds CSR chain) ----------------
__global__ void k_prep_misc(const float* __restrict__ edge_emb, const float* __restrict__ W_e,
                            const float* __restrict__ attn_e, const int* __restrict__ dst) {
    int b = blockIdx.x;
    if (b < 4) {
        int p = b * 8 + (threadIdx.x >> 5);
        int lane = threadIdx.x & 31;
        int t = p >> 2, h = p & 3;
        float acc0 = 0.f, acc1 = 0.f;
        int f0 = lane, f1 = lane + 32;
        #pragma unroll 4
        for (int k = 0; k < 64; k++) {
            float ek = edge_emb[t * 64 + k];
            acc0 += ek * W_e[k * 256 + h * 64 + f0];
            acc1 += ek * W_e[k * 256 + h * 64 + f1];
        }
        float v = acc0 * attn_e[h * 64 + f0] + acc1 * attn_e[h * 64 + f1];
        #pragma unroll
        for (int o = 16; o > 0; o >>= 1) v += __shfl_xor_sync(0xffffffffu, v, o);
        if (lane == 0) g_ee[t * 4 + h] = v;
    } else {
        int e = (b - 4) * 256 + threadIdx.x;
        if (e < NE) atomicAdd(&g_deg[dst[e]], 1);
    }
}

// ---------------- 3-phase parallel scan ----------------
__global__ void k_scan_a() {           // per-block partial sums
    __shared__ int ss[256];
    int i = blockIdx.x * 256 + threadIdx.x;
    int v = (i < NN) ? g_deg[i] : 0;
    ss[threadIdx.x] = v;
    __syncthreads();
    #pragma unroll
    for (int o = 128; o > 0; o >>= 1) {
        if (threadIdx.x < o) ss[threadIdx.x] += ss[threadIdx.x + o];
        __syncthreads();
    }
    if (threadIdx.x == 0) g_bsum[blockIdx.x] = ss[0];
}

__global__ void k_scan_b() {           // single block: exclusive scan of NB partials
    __shared__ int ss[256];
    int t = threadIdx.x;
    int v = (t < NB) ? g_bsum[t] : 0;
    ss[t] = v;
    __syncthreads();
    #pragma unroll
    for (int o = 1; o < 256; o <<= 1) {
        int u = (t >= o) ? ss[t - o] : 0;
        __syncthreads();
        ss[t] += u;
        __syncthreads();
    }
    if (t < NB) g_boff[t] = ss[t] - v;  // exclusive
}

__global__ void k_scan_c() {           // local scan + block offset
    __shared__ int ss[256];
    int i = blockIdx.x * 256 + threadIdx.x;
    int t = threadIdx.x;
    int v = (i < NN) ? g_deg[i] : 0;
    ss[t] = v;
    __syncthreads();
    #pragma unroll
    for (int o = 1; o < 256; o <<= 1) {
        int u = (t >= o) ? ss[t - o] : 0;
        __syncthreads();
        ss[t] += u;
        __syncthreads();
    }
    if (i < NN) {
        int off = g_boff[blockIdx.x] + ss[t] - v;  // exclusive
        g_off[i] = off;
        g_cur[i] = off;
    }
}

__global__ void k_scatter(const int* __restrict__ dst, const int* __restrict__ src,
                          const int* __restrict__ ef) {
    int e = blockIdx.x * blockDim.x + threadIdx.x;
    if (e < NE) {
        int p = atomicAdd(&g_cur[dst[e]], 1);
        g_epk[p] = make_int2(e, (src[e] << 3) | (ef[e] & 7));
    }
}

// ---------------- mma.sync fp16 GEMM (single pass), cp.async pipelined ----------------
#define ASTRIDE 80
#define BSTRIDE 272
#define ABUF 10240
#define BBUF 8704
#define SM_TOT2 (2*ABUF + 2*BBUF + 2048)

__device__ __forceinline__ void cpa16(uint32_t dst, const void* src) {
    asm volatile("cp.async.cg.shared.global [%0], [%1], 16;" :: "r"(dst), "l"(src));
}
__device__ __forceinline__ void ldsm_x4(uint32_t* r, uint32_t addr) {
    asm volatile("ldmatrix.sync.aligned.m8n8.x4.shared.b16 {%0,%1,%2,%3}, [%4];"
                 : "=r"(r[0]), "=r"(r[1]), "=r"(r[2]), "=r"(r[3]) : "r"(addr));
}
__device__ __forceinline__ void ldsm_x4t(uint32_t* r, uint32_t addr) {
    asm volatile("ldmatrix.sync.aligned.m8n8.x4.trans.shared.b16 {%0,%1,%2,%3}, [%4];"
                 : "=r"(r[0]), "=r"(r[1]), "=r"(r[2]), "=r"(r[3]) : "r"(addr));
}
__device__ __forceinline__ void mma_f16(float* c, const uint32_t* a, const uint32_t* b) {
    asm volatile(
        "mma.sync.aligned.m16n8k16.row.col.f32.f16.f16.f32 "
        "{%0,%1,%2,%3}, {%4,%5,%6,%7}, {%8,%9}, {%0,%1,%2,%3};"
        : "+f"(c[0]), "+f"(c[1]), "+f"(c[2]), "+f"(c[3])
        : "r"(a[0]), "r"(a[1]), "r"(a[2]), "r"(a[3]), "r"(b[0]), "r"(b[1]));
}

__global__ void __launch_bounds__(256, 2) k_gemm2(
    const float* __restrict__ attn_l, const float* __restrict__ attn_r)
{
    extern __shared__ __align__(16) char smem[];
    uint32_t uA = (uint32_t)__cvta_generic_to_shared(smem);
    uint32_t uB = uA + 2 * ABUF;
    float* s_attn = (float*)(smem + 2 * ABUF + 2 * BBUF);

    int tid = threadIdx.x, wid = tid >> 5, lane = tid & 31;
    int g = lane >> 2, tg = lane & 3;
    int bm = blockIdx.x * 128, bn = blockIdx.y * 128;
    int wm = (wid >> 1) * 32, wn = (wid & 1) * 64;

    uint32_t aBase = (wm + (lane & 7) + ((lane >> 3) & 1) * 8) * ASTRIDE + (lane >> 4) * 16;
    uint32_t bBase = (lane & 7) * BSTRIDE + wn * 2 + (lane >> 3) * 16;

    #pragma unroll
    for (int j = tid; j < 512; j += 256)
        s_attn[j] = (j < 256) ? attn_l[j] : attn_r[j - 256];

    float acc[2][8][4];
    #pragma unroll
    for (int am = 0; am < 2; am++)
        #pragma unroll
        for (int nb = 0; nb < 8; nb++)
            #pragma unroll
            for (int q = 0; q < 4; q++) acc[am][nb][q] = 0.f;

    auto load_tile = [&](int it, int bf) {
        int k0 = it * 32;
        #pragma unroll
        for (int j = 0; j < 2; j++) {
            int idx = tid + j * 256;
            int row = idx >> 2, q = idx & 3;
            int gr = min(bm + row, NN - 1);
            cpa16(uA + bf * ABUF + row * ASTRIDE + q * 16,
                  g_Ah + (size_t)gr * 256 + k0 + q * 8);
        }
        #pragma unroll
        for (int j = 0; j < 2; j++) {
            int idx = tid + j * 256;
            int k = idx >> 4, n16 = idx & 15;
            cpa16(uB + bf * BBUF + k * BSTRIDE + n16 * 16,
                  g_Bh + (size_t)(k0 + k) * 256 + bn + n16 * 8);
        }
    };

    load_tile(0, 0);
    asm volatile("cp.async.commit_group;" ::: "memory");

    for (int it = 0; it < 8; it++) {
        if (it < 7) {
            load_tile(it + 1, (it + 1) & 1);
            asm volatile("cp.async.commit_group;" ::: "memory");
            asm volatile("cp.async.wait_group 1;" ::: "memory");
        } else {
            asm volatile("cp.async.wait_group 0;" ::: "memory");
        }
        __syncthreads();

        uint32_t aoff = (it & 1) * ABUF + aBase, boff = (it & 1) * BBUF + bBase;
        #pragma unroll
        for (int ks = 0; ks < 2; ks++) {
            uint32_t ah[2][4];
            #pragma unroll
            for (int am = 0; am < 2; am++)
                ldsm_x4(ah[am], uA + aoff + am * 16 * ASTRIDE + ks * 32);
            uint32_t bh[8][2];
            #pragma unroll
            for (int ng = 0; ng < 2; ng++)
                #pragma unroll
                for (int kh = 0; kh < 2; kh++) {
                    uint32_t r[4];
                    uint32_t off = boff + (ks * 16 + kh * 8) * BSTRIDE + ng * 64;
                    ldsm_x4t(r, uB + off);
                    #pragma unroll
                    for (int jj = 0; jj < 4; jj++) bh[ng * 4 + jj][kh] = r[jj];
                }
            #pragma unroll
            for (int am = 0; am < 2; am++)
                #pragma unroll
                for (int nb = 0; nb < 8; nb++) mma_f16(acc[am][nb], ah[am], bh[nb]);
        }
        __syncthreads();
    }

    // ---- epilogue: store g_fth (fp16) + fused el/er ----
    int h = blockIdx.y * 2 + (wid & 1);
    float elp[2][2] = {{0.f, 0.f}, {0.f, 0.f}};
    float erp[2][2] = {{0.f, 0.f}, {0.f, 0.f}};

    #pragma unroll
    for (int am = 0; am < 2; am++) {
        #pragma unroll
        for (int rh = 0; rh < 2; rh++) {
            int row = bm + wm + am * 16 + g + rh * 8;
            if (row < NN) {
                #pragma unroll
                for (int nb = 0; nb < 8; nb++) {
                    float c0 = acc[am][nb][rh * 2 + 0];
                    float c1 = acc[am][nb][rh * 2 + 1];
                    int col = bn + wn + nb * 8 + 2 * tg;
                    *(__half2*)(g_fth + (size_t)row * 256 + col) = __floats2half2_rn(c0, c1);
                    int ch = nb * 8 + 2 * tg;
                    elp[am][rh] += c0 * s_attn[h * 64 + ch]       + c1 * s_attn[h * 64 + ch + 1];
                    erp[am][rh] += c0 * s_attn[256 + h * 64 + ch] + c1 * s_attn[256 + h * 64 + ch + 1];
                }
            }
        }
    }
    #pragma unroll
    for (int am = 0; am < 2; am++)
        #pragma unroll
        for (int rh = 0; rh < 2; rh++) {
            float e1 = elp[am][rh], e2 = erp[am][rh];
            #pragma unroll
            for (int o = 1; o < 4; o <<= 1) {
                e1 += __shfl_xor_sync(0xffffffffu, e1, o);
                e2 += __shfl_xor_sync(0xffffffffu, e2, o);
            }
            if (tg == 0) {
                int row = bm + wm + am * 16 + g + rh * 8;
                if (row < NN) {
                    g_el[row * 4 + h] = e1;
                    g_er[row * 4 + h] = e2;
                }
            }
        }
}

// ---------------- fused softmax + aggregation: one warp per dst node (R9 best) ----------------
__global__ void k_agg(float* __restrict__ out_rst, float* __restrict__ out_a) {
    int n = (blockIdx.x * blockDim.x + threadIdx.x) >> 5;
    int lane = threadIdx.x & 31;
    if (n >= NN) return;
    int off = g_off[n], dg = g_deg[n];

    float4 erv = *(const float4*)(g_er + n * 4);
    float s0 = 0.f, s1 = 0.f, s2 = 0.f, s3 = 0.f;

    for (int i = lane; i < dg; i += 32) {
        int pe = off + i;
        int2 pk = g_epk[pe];
        int s = pk.y >> 3, t = pk.y & 7;
        float4 elv = *(const float4*)(g_el + s * 4);
        float4 eev = *(const float4*)(g_ee + t * 4);
        float l0 = elv.x + erv.x + eev.x;
        float l1 = elv.y + erv.y + eev.y;
        float l2 = elv.z + erv.z + eev.z;
        float l3 = elv.w + erv.w + eev.w;
        l0 = l0 > 0.f ? l0 : NEG_SLOPE * l0;
        l1 = l1 > 0.f ? l1 : NEG_SLOPE * l1;
        l2 = l2 > 0.f ? l2 : NEG_SLOPE * l2;
        l3 = l3 > 0.f ? l3 : NEG_SLOPE * l3;
        float e0 = __expf(l0), e1 = __expf(l1), e2 = __expf(l2), e3 = __expf(l3);
        *(float4*)(g_aexp + (size_t)pe * 4) = make_float4(e0, e1, e2, e3);
        s0 += e0; s1 += e1; s2 += e2; s3 += e3;
    }
    #pragma unroll
    for (int o = 16; o > 0; o >>= 1) {
        s0 += __shfl_xor_sync(0xffffffffu, s0, o);
        s1 += __shfl_xor_sync(0xffffffffu, s1, o);
        s2 += __shfl_xor_sync(0xffffffffu, s2, o);
        s3 += __shfl_xor_sync(0xffffffffu, s3, o);
    }
    float i0 = (dg > 0) ? 1.f / s0 : 0.f;
    float i1 = (dg > 0) ? 1.f / s1 : 0.f;
    float i2 = (dg > 0) ? 1.f / s2 : 0.f;
    float i3 = (dg > 0) ? 1.f / s3 : 0.f;

    for (int i = lane; i < dg; i += 32) {
        int pe = off + i;
        float4 v = *(const float4*)(g_aexp + (size_t)pe * 4);
        v.x *= i0; v.y *= i1; v.z *= i2; v.w *= i3;
        int e = g_epk[pe].x;
        *(float4*)(out_a + (size_t)e * 4) = v;
    }

    float invh = (lane < 8) ? i0 : (lane < 16) ? i1 : (lane < 24) ? i2 : i3;
    float acc[8] = {0.f, 0.f, 0.f, 0.f, 0.f, 0.f, 0.f, 0.f};
    int myh = lane >> 3;
    int boff = lane * 8;
    const __half* ftb = g_fth + boff;
    #pragma unroll 4
    for (int i = 0; i < dg; i++) {
        int pe = off + i;
        int s = g_epk[pe].y >> 3;
        float a = g_aexp[(size_t)pe * 4 + myh] * invh;
        float4 xr = *(const float4*)(ftb + (size_t)s * 256);
        const __half2* hp = (const __half2*)&xr;
        #pragma unroll
        for (int q = 0; q < 4; q++) {
            float2 f = __half22float2(hp[q]);
            acc[q * 2 + 0] += a * f.x;
            acc[q * 2 + 1] += a * f.y;
        }
    }
    float4* op = (float4*)(out_rst + (size_t)n * 256 + boff);
    op[0] = make_float4(acc[0], acc[1], acc[2], acc[3]);
    op[1] = make_float4(acc[4], acc[5], acc[6], acc[7]);

    if (lane == 0) g_deg[n] = 0;
}

// ---------------- launch: fork-join streams (CSR chain overlaps GEMM) ----------------
extern "C" void kernel_launch(void* const* d_in, const int* in_sizes, int n_in,
                              void* d_out, int out_size) {
    const float* feat     = (const float*)d_in[0];
    const int*   efeat    = (const int*)  d_in[1];
    const int*   src      = (const int*)  d_in[2];
    const int*   dst      = (const int*)  d_in[3];
    const float* W_fc     = (const float*)d_in[4];
    const float* W_e      = (const float*)d_in[5];
    const float* edge_emb = (const float*)d_in[6];
    const float* attn_l   = (const float*)d_in[7];
    const float* attn_r   = (const float*)d_in[8];
    const float* attn_e   = (const float*)d_in[9];

    float* out_rst = (float*)d_out;
    float* out_a   = (float*)d_out + (size_t)NN * HD;

    static cudaStream_t s2 = nullptr;
    static cudaEvent_t evF = nullptr, evJ = nullptr;
    if (!s2) {
        cudaStreamCreateWithFlags(&s2, cudaStreamNonBlocking);
        cudaEventCreateWithFlags(&evF, cudaEventDisableTiming);
        cudaEventCreateWithFlags(&evJ, cudaEventDisableTiming);
        cudaFuncSetAttribute(k_gemm2, cudaFuncAttributeMaxDynamicSharedMemorySize, SM_TOT2);
    }

    // fork: side stream builds CSR (parallel scan) while main stream converts + GEMMs
    cudaEventRecord(evF, 0);
    cudaStreamWaitEvent(s2, evF, 0);

    k_prep_misc<<<3129, 256, 0, s2>>>(edge_emb, W_e, attn_e, dst);
    k_scan_a<<<NB, 256, 0, s2>>>();
    k_scan_b<<<1, 256, 0, s2>>>();
    k_scan_c<<<NB, 256, 0, s2>>>();
    k_scatter<<<3125, 256, 0, s2>>>(dst, src, efeat);
    cudaEventRecord(evJ, s2);

    k_prep_split<<<12564, 256>>>(feat, W_fc);
    k_gemm2<<<dim3(391, 2), 256, SM_TOT2>>>(attn_l, attn_r);

    // join: agg needs both CSR and GEMM results
    cudaStreamWaitEvent(0, evJ, 0);
    k_agg<<<(NN * 32 + 255) / 256, 256>>>(out_rst, out_a);
}